// round 16
// baseline (speedup 1.0000x reference)
#include <cuda_runtime.h>
#include <cstdint>
#include <cstddef>

// Problem constants (fixed by setup_inputs)
#define LL   4
#define BB   16
#define NN   4096
#define DD   1024
#define KK   20
#define KSEL 100
#define NCH2 16                  // 16 dim-chunks of 64 (all 4 layers fused per block)
#define NG   13                  // 8-row groups covering 100 (+4 pad) tokens
#define GSTR 12                  // floats per group slot (8 data + 4 pad -> conflict-free)
#define TSTR (NG*GSTR)           // 156 floats per j-row
#define NTRI 91                  // 13*14/2 upper-tri 8x8 tiles

// ---------------- scratch (device globals; no allocations) ----------------
__device__ int   g_topidx[BB*KSEL];
__device__ float g_gpart[(size_t)BB*NCH2*KSEL*KSEL];   // 10.24 MB partial grams
__device__ float g_avgtok[(size_t)BB*KSEL*DD];         // 6.55 MB layer-avg tokens
__device__ int   g_labels[BB*KSEL];
__device__ int   g_counts[BB*KK];

// linspace(0,99,20).astype(int32)
__constant__ int c_init[KK] = {0,5,10,15,20,26,31,36,41,46,52,57,62,67,72,78,83,88,93,99};

// packed f32x2 helpers
#define PACK2(d, s)   asm("mov.b64 %0, {%1, %1};" : "=l"(d) : "f"(s))
#define FMA2(acc, a, b) asm("fma.rn.f32x2 %0, %1, %2, %0;" : "+l"(acc) : "l"(a), "l"(b))
#define UNPK2(lo, hi, v) asm("mov.b64 {%0, %1}, %2;" : "=f"(lo), "=f"(hi) : "l"(v))

// ---------------- kernel A: fused score + stable sorted top-100 ----------
__global__ void __launch_bounds__(512) topk_kernel(const float* __restrict__ am) {
    int b = blockIdx.x, tid = threadIdx.x;
    int lane = tid & 31, wid = tid >> 5;               // 16 warps
    __shared__ unsigned long long keys[NN];            // 32 KB
    __shared__ unsigned long long segmax_sm[16];

    const float2* a2 = (const float2*)am;
    for (int e = tid; e < NN; e += 512) {
        float s0 = 0.f, s1 = 0.f;
        #pragma unroll
        for (int l = 0; l < LL; l++) {                 // sequential l-order sum
            float2 v = a2[(size_t)l*BB*NN + b*NN + e];
            s0 += v.x; s1 += v.y;
        }
        float m0 = s0*0.25f, m1 = s1*0.25f;
        float mx = fmaxf(m0, m1);
        float e0 = expf(m0 - mx), e1 = expf(m1 - mx);
        float prob = e1 / (e0 + e1);
        unsigned u = __float_as_uint(prob);
        u = (u & 0x80000000u) ? ~u : (u | 0x80000000u);
        keys[e] = (((unsigned long long)u) << 32) | (unsigned)(NN - 1 - e);
    }
    __syncthreads();

    {
        unsigned long long m = 0ULL;
        int base = wid << 8;
        #pragma unroll
        for (int q = 0; q < 8; q++) {
            unsigned long long k = keys[base + q*32 + lane];
            if (k > m) m = k;
        }
        #pragma unroll
        for (int o = 16; o > 0; o >>= 1) {
            unsigned long long t = __shfl_down_sync(0xffffffffu, m, o);
            if (t > m) m = t;
        }
        if (lane == 0) segmax_sm[wid] = m;
    }
    __syncthreads();

    if (wid != 0) return;                              // warp 0 does the rounds

    unsigned long long sg[16];
    #pragma unroll
    for (int s = 0; s < 16; s++) sg[s] = segmax_sm[s];

    for (int r = 0; r < KSEL; r++) {
        unsigned long long mm = sg[0];
        #pragma unroll
        for (int s = 1; s < 16; s++) if (sg[s] > mm) mm = sg[s];
        int idx = (NN - 1) - (int)(unsigned)(mm & 0xffffffffULL);
        if (lane == 0) {
            g_topidx[b*KSEL + r] = idx;
            keys[idx] = 0ULL;
        }
        __syncwarp();
        int s = idx >> 8;
        unsigned long long nm = 0ULL;
        int base = s << 8;
        #pragma unroll
        for (int q = 0; q < 8; q++) {
            unsigned long long k = keys[base + q*32 + lane];
            if (k > nm) nm = k;
        }
        #pragma unroll
        for (int o = 16; o > 0; o >>= 1) {
            unsigned long long t = __shfl_xor_sync(0xffffffffu, nm, o);
            if (t > nm) nm = t;
        }
        #pragma unroll
        for (int q = 0; q < 16; q++)
            if (s == q) sg[q] = nm;
    }
}

// ---------------- kernel B: layer-fused partial Gram + avgtok -------------
// grid (NCH2, BB); 64-dim chunk across all 4 layers (K=256 j-rows).
// Upper-tri 8x8 register tiles with packed fma.rn.f32x2; mirrored store.
__global__ void __launch_bounds__(256) gram_kernel(const float* __restrict__ x) {
    extern __shared__ float tileT[];                   // [256][TSTR]
    int b = blockIdx.y, c = blockIdx.x;
    int off = c * 64;
    __shared__ int sidx[KSEL];
    int tid = threadIdx.x;
    if (tid < KSEL) sidx[tid] = g_topidx[b*KSEL + tid];
    __syncthreads();

    const size_t LS = (size_t)BB*NN*DD;
    for (int v = tid; v < KSEL*16; v += 256) {
        int row = v >> 4, c4 = v & 15;
        size_t base = ((size_t)b*NN + sidx[row])*DD + off + c4*4;
        float4 f0 = __ldg((const float4*)(x + base));
        float4 f1 = __ldg((const float4*)(x + base +   LS));
        float4 f2 = __ldg((const float4*)(x + base + 2*LS));
        float4 f3 = __ldg((const float4*)(x + base + 3*LS));
        int slot = (row >> 3) * GSTR + (row & 7);      // group slot for this token
        int j = c4 * 4;
        tileT[(0*64 + j+0)*TSTR + slot] = f0.x; tileT[(0*64 + j+1)*TSTR + slot] = f0.y;
        tileT[(0*64 + j+2)*TSTR + slot] = f0.z; tileT[(0*64 + j+3)*TSTR + slot] = f0.w;
        tileT[(1*64 + j+0)*TSTR + slot] = f1.x; tileT[(1*64 + j+1)*TSTR + slot] = f1.y;
        tileT[(1*64 + j+2)*TSTR + slot] = f1.z; tileT[(1*64 + j+3)*TSTR + slot] = f1.w;
        tileT[(2*64 + j+0)*TSTR + slot] = f2.x; tileT[(2*64 + j+1)*TSTR + slot] = f2.y;
        tileT[(2*64 + j+2)*TSTR + slot] = f2.z; tileT[(2*64 + j+3)*TSTR + slot] = f2.w;
        tileT[(3*64 + j+0)*TSTR + slot] = f3.x; tileT[(3*64 + j+1)*TSTR + slot] = f3.y;
        tileT[(3*64 + j+2)*TSTR + slot] = f3.z; tileT[(3*64 + j+3)*TSTR + slot] = f3.w;
        float4 avg;
        avg.x = (((f0.x + f1.x) + f2.x) + f3.x) * 0.25f;
        avg.y = (((f0.y + f1.y) + f2.y) + f3.y) * 0.25f;
        avg.z = (((f0.z + f1.z) + f2.z) + f3.z) * 0.25f;
        avg.w = (((f0.w + f1.w) + f2.w) + f3.w) * 0.25f;
        *(float4*)(g_avgtok + ((size_t)(b*KSEL + row))*DD + off + c4*4) = avg;
    }
    // zero padding tokens 100..103 (group 12, slots 4..7) for every j-row
    for (int v = tid; v < 4*256; v += 256) {
        int r = v & 3, j = v >> 2;
        tileT[j*TSTR + 12*GSTR + 4 + r] = 0.f;
    }
    __syncthreads();

    if (tid < NTRI) {
        int ti = 0, r = tid;
        while (r >= NG - ti) { r -= NG - ti; ti++; }
        int tj = ti + r;
        const int ao = ti * GSTR, co = tj * GSTR;

        unsigned long long acc[8][4];
        #pragma unroll
        for (int p = 0; p < 8; p++)
            #pragma unroll
            for (int q = 0; q < 4; q++) acc[p][q] = 0ULL;

        #pragma unroll 4
        for (int j = 0; j < 256; j++) {
            const float* rowp = tileT + j*TSTR;
            float4 a0 = *(const float4*)(rowp + ao);
            float4 a1 = *(const float4*)(rowp + ao + 4);
            ulonglong2 c0 = *(const ulonglong2*)(rowp + co);
            ulonglong2 c1 = *(const ulonglong2*)(rowp + co + 4);
            float av[8] = {a0.x,a0.y,a0.z,a0.w,a1.x,a1.y,a1.z,a1.w};
            #pragma unroll
            for (int p = 0; p < 8; p++) {
                unsigned long long aa;
                PACK2(aa, av[p]);
                FMA2(acc[p][0], aa, c0.x);
                FMA2(acc[p][1], aa, c0.y);
                FMA2(acc[p][2], aa, c1.x);
                FMA2(acc[p][3], aa, c1.y);
            }
        }

        float* gp = g_gpart + ((size_t)(b*NCH2 + c)) * (KSEL*KSEL);
        #pragma unroll
        for (int p = 0; p < 8; p++) {
            int rr = 8*ti + p;
            if (rr >= KSEL) break;
            #pragma unroll
            for (int q = 0; q < 4; q++) {
                float lo, hi;
                UNPK2(lo, hi, acc[p][q]);
                int cc = 8*tj + 2*q;
                if (cc < KSEL)     gp[rr*KSEL + cc]     = lo;
                if (cc + 1 < KSEL) gp[rr*KSEL + cc + 1] = hi;
                if (ti != tj) {
                    if (cc < KSEL)     gp[cc*KSEL + rr]     = lo;
                    if (cc + 1 < KSEL) gp[(cc+1)*KSEL + rr] = hi;
                }
            }
        }
    }
}

// ---------------- kernel C: Lloyd k-means (fused reduce, early exit) ------
__global__ void __launch_bounds__(640) kmeans_kernel() {
    int b = blockIdx.x, tid = threadIdx.x;
    int lane = tid & 31, wid = tid >> 5;               // 20 warps
    __shared__ float Gsm[KSEL*KSEL];                   // 40000 B
    __shared__ float Psm[KK*KSEL];                     //  8000 B  P[k][i] = x_i . c_k
    __shared__ float qsm[KK];                          //  |c_k|^2
    __shared__ int   labsm[128];
    __shared__ int   changedsm;

    // fused reduction of the 16 partial grams (fixed ascending order)
    {
        const float4* gp = (const float4*)g_gpart + (size_t)b*NCH2*2500;
        for (int e = tid; e < 2500; e += 640) {
            float4 a = make_float4(0.f, 0.f, 0.f, 0.f);
            #pragma unroll
            for (int c = 0; c < NCH2; c++) {
                float4 v = gp[(size_t)c*2500 + e];
                a.x += v.x; a.y += v.y; a.z += v.z; a.w += v.w;
            }
            ((float4*)Gsm)[e] = a;
        }
    }
    __syncthreads();

    for (int t = tid; t < KK*KSEL; t += 640) {
        int k = t / KSEL, i = t - k*KSEL;
        Psm[t] = Gsm[i*KSEL + c_init[k]];
    }
    if (tid < KK) qsm[tid] = Gsm[c_init[tid]*KSEL + c_init[tid]];
    if (tid < 128) labsm[tid] = -1;
    if (tid == 0) changedsm = 0;
    __syncthreads();

    float diag = (tid < KSEL) ? Gsm[tid*KSEL + tid] : 0.f;

    for (int it = 0; ; it++) {
        // ---- assign via packed u64 keys: (enc(dist) << 32) | k, umin ----
        if (tid < KSEL) {
            unsigned long long kmin = ~0ULL;
            #pragma unroll
            for (int k = 0; k < KK; k++) {
                float s = fmaf(-2.f, Psm[k*KSEL + tid], diag) + qsm[k];
                unsigned u = __float_as_uint(s);
                u = (u & 0x80000000u) ? ~u : (u | 0x80000000u);
                unsigned long long key = ((unsigned long long)u << 32) | (unsigned)k;
                if (key < kmin) kmin = key;            // ties -> lower k
            }
            int lab = (int)(unsigned)(kmin & 0xffffffffULL);
            if (lab != labsm[tid]) changedsm = 1;
            labsm[tid] = lab;
        }
        __syncthreads();
        if (it == 10 || changedsm == 0) break;         // fixed point => exact
        if (tid == 0) changedsm = 0;

        // ---- update: warp k rebuilds its mask and recomputes P[k], q[k] ----
        {
            const int k = wid;
            int l0 = labsm[lane], l1 = labsm[lane + 32], l2 = labsm[lane + 64];
            int l3 = (lane < 4) ? labsm[lane + 96] : -1;
            unsigned m0 = __ballot_sync(0xffffffffu, l0 == k);
            unsigned m1 = __ballot_sync(0xffffffffu, l1 == k);
            unsigned m2 = __ballot_sync(0xffffffffu, l2 == k);
            unsigned m3 = __ballot_sync(0xffffffffu, l3 == k);
            const int cnt = __popc(m0)+__popc(m1)+__popc(m2)+__popc(m3);
            if (cnt > 0) {
                float s0=0.f, s1=0.f, s2=0.f, s3=0.f;
                unsigned mm[4] = {m0, m1, m2, m3};
                #pragma unroll
                for (int c4 = 0; c4 < 4; c4++) {
                    unsigned m = mm[c4];
                    while (m) {                         // ascending j: fixed order
                        int j = (c4 << 5) + __ffs(m) - 1;
                        m &= m - 1;
                        const float* row = Gsm + j*KSEL;
                        s0 += row[lane];
                        s1 += row[lane + 32];
                        s2 += row[lane + 64];
                        if (lane < 4) s3 += row[lane + 96];
                    }
                }
                float t = 0.f;
                if ((m0 >> lane) & 1u) t += s0;
                if ((m1 >> lane) & 1u) t += s1;
                if ((m2 >> lane) & 1u) t += s2;
                if (lane < 4 && ((m3 >> lane) & 1u)) t += s3;
                #pragma unroll
                for (int o = 16; o > 0; o >>= 1)
                    t += __shfl_down_sync(0xffffffffu, t, o);
                float inv = 1.0f / (float)cnt;          // one IEEE div per warp
                Psm[k*KSEL + lane]      = s0 * inv;
                Psm[k*KSEL + lane + 32] = s1 * inv;
                Psm[k*KSEL + lane + 64] = s2 * inv;
                if (lane < 4) Psm[k*KSEL + lane + 96] = s3 * inv;
                if (lane == 0) qsm[k] = t * inv * inv;
            }
        }
        __syncthreads();
    }

    if (tid < KSEL) g_labels[b*KSEL + tid] = labsm[tid];
    {
        int l0 = labsm[lane], l1 = labsm[lane + 32], l2 = labsm[lane + 64];
        int l3 = (lane < 4) ? labsm[lane + 96] : -1;
        unsigned m0 = __ballot_sync(0xffffffffu, l0 == wid);
        unsigned m1 = __ballot_sync(0xffffffffu, l1 == wid);
        unsigned m2 = __ballot_sync(0xffffffffu, l2 == wid);
        unsigned m3 = __ballot_sync(0xffffffffu, l3 == wid);
        if (lane == 0)
            g_counts[b*KK + wid] = __popc(m0)+__popc(m1)+__popc(m2)+__popc(m3);
    }
}

// ---------------- kernel D: fused centers + L2 normalize -------------------
// one block per batch; 256 threads, one float4 per thread (1024 dims).
__global__ void __launch_bounds__(256) centersnorm_kernel(float* __restrict__ out) {
    int b = blockIdx.x, tid = threadIdx.x;
    __shared__ float w[KSEL];
    __shared__ float red[256];
    if (tid < KSEL) {
        int lab = g_labels[b*KSEL + tid];
        int c   = g_counts[b*KK + lab];
        w[tid]  = 1.0f / (20.0f * (float)c);
    }
    __syncthreads();

    const float4* at = (const float4*)g_avgtok + (size_t)b*KSEL*(DD/4) + tid;
    float ax = 0.f, ay = 0.f, az = 0.f, aw = 0.f;
    #pragma unroll 4
    for (int i = 0; i < KSEL; i++) {
        float4 v = at[(size_t)i*(DD/4)];
        float wi = w[i];
        ax += v.x*wi; ay += v.y*wi; az += v.z*wi; aw += v.w*wi;
    }
    red[tid] = ((ax*ax + ay*ay) + (az*az + aw*aw));
    __syncthreads();
    #pragma unroll
    for (int s = 128; s > 0; s >>= 1) {
        if (tid < s) red[tid] += red[tid + s];
        __syncthreads();
    }
    float inv = 1.0f / fmaxf(sqrtf(red[0]), 1e-12f);
    ((float4*)out)[(size_t)b*(DD/4) + tid] =
        make_float4(ax*inv, ay*inv, az*inv, aw*inv);
}

// ---------------- launcher -------------------------------------------------
extern "C" void kernel_launch(void* const* d_in, const int* in_sizes, int n_in,
                              void* d_out, int out_size) {
    const float* patch = nullptr;
    const float* am    = nullptr;
    for (int i = 0; i < n_in; i++) {
        if (in_sizes[i] == LL*BB*NN*DD)      patch = (const float*)d_in[i];
        else if (in_sizes[i] == LL*BB*NN*2)  am    = (const float*)d_in[i];
    }
    if (!patch || !am) return;

    const int GRAM_SMEM = 256 * TSTR * 4;              // 159,744 B dynamic
    cudaFuncSetAttribute(gram_kernel, cudaFuncAttributeMaxDynamicSharedMemorySize, GRAM_SMEM);

    topk_kernel       <<< BB, 512 >>>(am);
    gram_kernel       <<< dim3(NCH2, BB), 256, GRAM_SMEM >>>(patch);
    kmeans_kernel     <<< BB, 640 >>>();
    centersnorm_kernel<<< BB, 256 >>>((float*)d_out);
}

// round 17
// speedup vs baseline: 1.5536x; 1.5536x over previous
#include <cuda_runtime.h>
#include <cstdint>
#include <cstddef>

// Problem constants (fixed by setup_inputs)
#define LL   4
#define BB   16
#define NN   4096
#define DD   1024
#define KK   20
#define KSEL 100
#define NCH2 16                  // 16 dim-chunks of 64 (all 4 layers fused per block)
#define NG   13                  // 8-row groups covering 100 (+4 pad) tokens
#define GSTR 12                  // floats per group slot (8 data + 4 pad -> conflict-free)
#define TSTR (NG*GSTR)           // 156 floats per j-row
#define NTRI 91                  // 13*14/2 upper-tri 8x8 tiles

// ---------------- scratch (device globals; no allocations) ----------------
__device__ int   g_topidx[BB*KSEL];
__device__ float g_gpart[(size_t)BB*NCH2*KSEL*KSEL];   // 10.24 MB partial grams
__device__ float g_avgtok[(size_t)BB*KSEL*DD];         // 6.55 MB layer-avg tokens
__device__ int   g_labels[BB*KSEL];
__device__ int   g_counts[BB*KK];

// linspace(0,99,20).astype(int32)
__constant__ int c_init[KK] = {0,5,10,15,20,26,31,36,41,46,52,57,62,67,72,78,83,88,93,99};

// packed f32x2 helpers
#define PACK2(d, s)   asm("mov.b64 %0, {%1, %1};" : "=l"(d) : "f"(s))
#define FMA2(acc, a, b) asm("fma.rn.f32x2 %0, %1, %2, %0;" : "+l"(acc) : "l"(a), "l"(b))
#define UNPK2(lo, hi, v) asm("mov.b64 {%0, %1}, %2;" : "=f"(lo), "=f"(hi) : "l"(v))

// ---------------- kernel A: fused score + stable sorted top-100 ----------
__global__ void __launch_bounds__(512) topk_kernel(const float* __restrict__ am) {
    int b = blockIdx.x, tid = threadIdx.x;
    int lane = tid & 31, wid = tid >> 5;               // 16 warps
    __shared__ unsigned long long keys[NN];            // 32 KB
    __shared__ unsigned long long segmax_sm[16];

    const float2* a2 = (const float2*)am;
    for (int e = tid; e < NN; e += 512) {
        float s0 = 0.f, s1 = 0.f;
        #pragma unroll
        for (int l = 0; l < LL; l++) {                 // sequential l-order sum
            float2 v = a2[(size_t)l*BB*NN + b*NN + e];
            s0 += v.x; s1 += v.y;
        }
        float m0 = s0*0.25f, m1 = s1*0.25f;
        float mx = fmaxf(m0, m1);
        float e0 = expf(m0 - mx), e1 = expf(m1 - mx);
        float prob = e1 / (e0 + e1);
        unsigned u = __float_as_uint(prob);
        u = (u & 0x80000000u) ? ~u : (u | 0x80000000u);
        keys[e] = (((unsigned long long)u) << 32) | (unsigned)(NN - 1 - e);
    }
    __syncthreads();

    {
        unsigned long long m = 0ULL;
        int base = wid << 8;
        #pragma unroll
        for (int q = 0; q < 8; q++) {
            unsigned long long k = keys[base + q*32 + lane];
            if (k > m) m = k;
        }
        #pragma unroll
        for (int o = 16; o > 0; o >>= 1) {
            unsigned long long t = __shfl_down_sync(0xffffffffu, m, o);
            if (t > m) m = t;
        }
        if (lane == 0) segmax_sm[wid] = m;
    }
    __syncthreads();

    if (wid != 0) return;                              // warp 0 does the rounds

    unsigned long long sg[16];
    #pragma unroll
    for (int s = 0; s < 16; s++) sg[s] = segmax_sm[s];

    for (int r = 0; r < KSEL; r++) {
        unsigned long long mm = sg[0];
        #pragma unroll
        for (int s = 1; s < 16; s++) if (sg[s] > mm) mm = sg[s];
        int idx = (NN - 1) - (int)(unsigned)(mm & 0xffffffffULL);
        if (lane == 0) {
            g_topidx[b*KSEL + r] = idx;
            keys[idx] = 0ULL;
        }
        __syncwarp();
        int s = idx >> 8;
        unsigned long long nm = 0ULL;
        int base = s << 8;
        #pragma unroll
        for (int q = 0; q < 8; q++) {
            unsigned long long k = keys[base + q*32 + lane];
            if (k > nm) nm = k;
        }
        #pragma unroll
        for (int o = 16; o > 0; o >>= 1) {
            unsigned long long t = __shfl_xor_sync(0xffffffffu, nm, o);
            if (t > nm) nm = t;
        }
        #pragma unroll
        for (int q = 0; q < 16; q++)
            if (s == q) sg[q] = nm;
    }
}

// ---------------- kernel B: layer-fused partial Gram + avgtok -------------
// grid (NCH2, BB); 64-dim chunk across all 4 layers (K=256 j-rows).
// Upper-tri 8x8 register tiles with packed fma.rn.f32x2; mirrored store.
__global__ void __launch_bounds__(256) gram_kernel(const float* __restrict__ x) {
    extern __shared__ float tileT[];                   // [256][TSTR]
    int b = blockIdx.y, c = blockIdx.x;
    int off = c * 64;
    __shared__ int sidx[KSEL];
    int tid = threadIdx.x;
    if (tid < KSEL) sidx[tid] = g_topidx[b*KSEL + tid];
    __syncthreads();

    const size_t LS = (size_t)BB*NN*DD;
    for (int v = tid; v < KSEL*16; v += 256) {
        int row = v >> 4, c4 = v & 15;
        size_t base = ((size_t)b*NN + sidx[row])*DD + off + c4*4;
        float4 f0 = __ldg((const float4*)(x + base));
        float4 f1 = __ldg((const float4*)(x + base +   LS));
        float4 f2 = __ldg((const float4*)(x + base + 2*LS));
        float4 f3 = __ldg((const float4*)(x + base + 3*LS));
        int slot = (row >> 3) * GSTR + (row & 7);      // group slot for this token
        int j = c4 * 4;
        tileT[(0*64 + j+0)*TSTR + slot] = f0.x; tileT[(0*64 + j+1)*TSTR + slot] = f0.y;
        tileT[(0*64 + j+2)*TSTR + slot] = f0.z; tileT[(0*64 + j+3)*TSTR + slot] = f0.w;
        tileT[(1*64 + j+0)*TSTR + slot] = f1.x; tileT[(1*64 + j+1)*TSTR + slot] = f1.y;
        tileT[(1*64 + j+2)*TSTR + slot] = f1.z; tileT[(1*64 + j+3)*TSTR + slot] = f1.w;
        tileT[(2*64 + j+0)*TSTR + slot] = f2.x; tileT[(2*64 + j+1)*TSTR + slot] = f2.y;
        tileT[(2*64 + j+2)*TSTR + slot] = f2.z; tileT[(2*64 + j+3)*TSTR + slot] = f2.w;
        tileT[(3*64 + j+0)*TSTR + slot] = f3.x; tileT[(3*64 + j+1)*TSTR + slot] = f3.y;
        tileT[(3*64 + j+2)*TSTR + slot] = f3.z; tileT[(3*64 + j+3)*TSTR + slot] = f3.w;
        float4 avg;
        avg.x = (((f0.x + f1.x) + f2.x) + f3.x) * 0.25f;
        avg.y = (((f0.y + f1.y) + f2.y) + f3.y) * 0.25f;
        avg.z = (((f0.z + f1.z) + f2.z) + f3.z) * 0.25f;
        avg.w = (((f0.w + f1.w) + f2.w) + f3.w) * 0.25f;
        *(float4*)(g_avgtok + ((size_t)(b*KSEL + row))*DD + off + c4*4) = avg;
    }
    // zero padding tokens 100..103 (group 12, slots 4..7) for every j-row
    for (int v = tid; v < 4*256; v += 256) {
        int r = v & 3, j = v >> 2;
        tileT[j*TSTR + 12*GSTR + 4 + r] = 0.f;
    }
    __syncthreads();

    if (tid < NTRI) {
        int ti = 0, r = tid;
        while (r >= NG - ti) { r -= NG - ti; ti++; }
        int tj = ti + r;
        const int ao = ti * GSTR, co = tj * GSTR;

        unsigned long long acc[8][4];
        #pragma unroll
        for (int p = 0; p < 8; p++)
            #pragma unroll
            for (int q = 0; q < 4; q++) acc[p][q] = 0ULL;

        #pragma unroll 4
        for (int j = 0; j < 256; j++) {
            const float* rowp = tileT + j*TSTR;
            float4 a0 = *(const float4*)(rowp + ao);
            float4 a1 = *(const float4*)(rowp + ao + 4);
            ulonglong2 c0 = *(const ulonglong2*)(rowp + co);
            ulonglong2 c1 = *(const ulonglong2*)(rowp + co + 4);
            float av[8] = {a0.x,a0.y,a0.z,a0.w,a1.x,a1.y,a1.z,a1.w};
            #pragma unroll
            for (int p = 0; p < 8; p++) {
                unsigned long long aa;
                PACK2(aa, av[p]);
                FMA2(acc[p][0], aa, c0.x);
                FMA2(acc[p][1], aa, c0.y);
                FMA2(acc[p][2], aa, c1.x);
                FMA2(acc[p][3], aa, c1.y);
            }
        }

        float* gp = g_gpart + ((size_t)(b*NCH2 + c)) * (KSEL*KSEL);
        #pragma unroll
        for (int p = 0; p < 8; p++) {
            int rr = 8*ti + p;
            if (rr >= KSEL) break;
            #pragma unroll
            for (int q = 0; q < 4; q++) {
                float lo, hi;
                UNPK2(lo, hi, acc[p][q]);
                int cc = 8*tj + 2*q;
                if (cc < KSEL)     gp[rr*KSEL + cc]     = lo;
                if (cc + 1 < KSEL) gp[rr*KSEL + cc + 1] = hi;
                if (ti != tj) {
                    if (cc < KSEL)     gp[cc*KSEL + rr]     = lo;
                    if (cc + 1 < KSEL) gp[(cc+1)*KSEL + rr] = hi;
                }
            }
        }
    }
}

// ---------------- kernel C: Lloyd k-means (fused reduce, early exit) ------
__global__ void __launch_bounds__(640) kmeans_kernel() {
    int b = blockIdx.x, tid = threadIdx.x;
    int lane = tid & 31, wid = tid >> 5;               // 20 warps
    __shared__ float Gsm[KSEL*KSEL];                   // 40000 B
    __shared__ float Psm[KK*KSEL];                     //  8000 B  P[k][i] = x_i . c_k
    __shared__ float qsm[KK];                          //  |c_k|^2
    __shared__ int   labsm[128];
    __shared__ int   changedsm;

    // fused reduction of the 16 partial grams (fixed ascending order)
    {
        const float4* gp = (const float4*)g_gpart + (size_t)b*NCH2*2500;
        for (int e = tid; e < 2500; e += 640) {
            float4 a = make_float4(0.f, 0.f, 0.f, 0.f);
            #pragma unroll
            for (int c = 0; c < NCH2; c++) {
                float4 v = gp[(size_t)c*2500 + e];
                a.x += v.x; a.y += v.y; a.z += v.z; a.w += v.w;
            }
            ((float4*)Gsm)[e] = a;
        }
    }
    __syncthreads();

    for (int t = tid; t < KK*KSEL; t += 640) {
        int k = t / KSEL, i = t - k*KSEL;
        Psm[t] = Gsm[i*KSEL + c_init[k]];
    }
    if (tid < KK) qsm[tid] = Gsm[c_init[tid]*KSEL + c_init[tid]];
    if (tid < 128) labsm[tid] = -1;
    if (tid == 0) changedsm = 0;
    __syncthreads();

    float diag = (tid < KSEL) ? Gsm[tid*KSEL + tid] : 0.f;

    for (int it = 0; ; it++) {
        // ---- assign via packed u64 keys: (enc(dist) << 32) | k, umin ----
        if (tid < KSEL) {
            unsigned long long kmin = ~0ULL;
            #pragma unroll
            for (int k = 0; k < KK; k++) {
                float s = fmaf(-2.f, Psm[k*KSEL + tid], diag) + qsm[k];
                unsigned u = __float_as_uint(s);
                u = (u & 0x80000000u) ? ~u : (u | 0x80000000u);
                unsigned long long key = ((unsigned long long)u << 32) | (unsigned)k;
                if (key < kmin) kmin = key;            // ties -> lower k
            }
            int lab = (int)(unsigned)(kmin & 0xffffffffULL);
            if (lab != labsm[tid]) changedsm = 1;
            labsm[tid] = lab;
        }
        __syncthreads();
        if (it == 10 || changedsm == 0) break;         // fixed point => exact
        if (tid == 0) changedsm = 0;

        // ---- update: warp k rebuilds its mask and recomputes P[k], q[k] ----
        {
            const int k = wid;
            int l0 = labsm[lane], l1 = labsm[lane + 32], l2 = labsm[lane + 64];
            int l3 = (lane < 4) ? labsm[lane + 96] : -1;
            unsigned m0 = __ballot_sync(0xffffffffu, l0 == k);
            unsigned m1 = __ballot_sync(0xffffffffu, l1 == k);
            unsigned m2 = __ballot_sync(0xffffffffu, l2 == k);
            unsigned m3 = __ballot_sync(0xffffffffu, l3 == k);
            const int cnt = __popc(m0)+__popc(m1)+__popc(m2)+__popc(m3);
            if (cnt > 0) {
                float s0=0.f, s1=0.f, s2=0.f, s3=0.f;
                unsigned mm[4] = {m0, m1, m2, m3};
                #pragma unroll
                for (int c4 = 0; c4 < 4; c4++) {
                    unsigned m = mm[c4];
                    while (m) {                         // ascending j: fixed order
                        int j = (c4 << 5) + __ffs(m) - 1;
                        m &= m - 1;
                        const float* row = Gsm + j*KSEL;
                        s0 += row[lane];
                        s1 += row[lane + 32];
                        s2 += row[lane + 64];
                        if (lane < 4) s3 += row[lane + 96];
                    }
                }
                float t = 0.f;
                if ((m0 >> lane) & 1u) t += s0;
                if ((m1 >> lane) & 1u) t += s1;
                if ((m2 >> lane) & 1u) t += s2;
                if (lane < 4 && ((m3 >> lane) & 1u)) t += s3;
                #pragma unroll
                for (int o = 16; o > 0; o >>= 1)
                    t += __shfl_down_sync(0xffffffffu, t, o);
                float inv = 1.0f / (float)cnt;          // one IEEE div per warp
                Psm[k*KSEL + lane]      = s0 * inv;
                Psm[k*KSEL + lane + 32] = s1 * inv;
                Psm[k*KSEL + lane + 64] = s2 * inv;
                if (lane < 4) Psm[k*KSEL + lane + 96] = s3 * inv;
                if (lane == 0) qsm[k] = t * inv * inv;
            }
        }
        __syncthreads();
    }

    if (tid < KSEL) g_labels[b*KSEL + tid] = labsm[tid];
    {
        int l0 = labsm[lane], l1 = labsm[lane + 32], l2 = labsm[lane + 64];
        int l3 = (lane < 4) ? labsm[lane + 96] : -1;
        unsigned m0 = __ballot_sync(0xffffffffu, l0 == wid);
        unsigned m1 = __ballot_sync(0xffffffffu, l1 == wid);
        unsigned m2 = __ballot_sync(0xffffffffu, l2 == wid);
        unsigned m3 = __ballot_sync(0xffffffffu, l3 == wid);
        if (lane == 0)
            g_counts[b*KK + wid] = __popc(m0)+__popc(m1)+__popc(m2)+__popc(m3);
    }
}

// ---------------- kernel D: fused centers + L2 normalize -------------------
// one block per batch; 256 threads, one float4 per thread (1024 dims).
__global__ void __launch_bounds__(256) centersnorm_kernel(float* __restrict__ out) {
    int b = blockIdx.x, tid = threadIdx.x;
    __shared__ float w[KSEL];
    __shared__ float red[256];
    if (tid < KSEL) {
        int lab = g_labels[b*KSEL + tid];
        int c   = g_counts[b*KK + lab];
        w[tid]  = 1.0f / (20.0f * (float)c);
    }
    __syncthreads();

    const float4* at = (const float4*)g_avgtok + (size_t)b*KSEL*(DD/4) + tid;
    float ax = 0.f, ay = 0.f, az = 0.f, aw = 0.f;
    #pragma unroll 4
    for (int i = 0; i < KSEL; i++) {
        float4 v = at[(size_t)i*(DD/4)];
        float wi = w[i];
        ax += v.x*wi; ay += v.y*wi; az += v.z*wi; aw += v.w*wi;
    }
    red[tid] = ((ax*ax + ay*ay) + (az*az + aw*aw));
    __syncthreads();
    #pragma unroll
    for (int s = 128; s > 0; s >>= 1) {
        if (tid < s) red[tid] += red[tid + s];
        __syncthreads();
    }
    float inv = 1.0f / fmaxf(sqrtf(red[0]), 1e-12f);
    ((float4*)out)[(size_t)b*(DD/4) + tid] =
        make_float4(ax*inv, ay*inv, az*inv, aw*inv);
}

// ---------------- launcher -------------------------------------------------
extern "C" void kernel_launch(void* const* d_in, const int* in_sizes, int n_in,
                              void* d_out, int out_size) {
    const float* patch = nullptr;
    const float* am    = nullptr;
    for (int i = 0; i < n_in; i++) {
        if (in_sizes[i] == LL*BB*NN*DD)      patch = (const float*)d_in[i];
        else if (in_sizes[i] == LL*BB*NN*2)  am    = (const float*)d_in[i];
    }
    if (!patch || !am) return;

    const int GRAM_SMEM = 256 * TSTR * 4;              // 159,744 B dynamic
    cudaFuncSetAttribute(gram_kernel, cudaFuncAttributeMaxDynamicSharedMemorySize, GRAM_SMEM);

    topk_kernel       <<< BB, 512 >>>(am);
    gram_kernel       <<< dim3(NCH2, BB), 256, GRAM_SMEM >>>(patch);
    kmeans_kernel     <<< BB, 640 >>>();
    centersnorm_kernel<<< BB, 256 >>>((float*)d_out);
}